// round 6
// baseline (speedup 1.0000x reference)
#include <cuda_runtime.h>
#include <cstdint>

// Problem constants (fixed by the dataset: N=100000, E=1600000, D=64)
#define NMAX 100000
#define D    64
#define D2   128

// ---------------- scratch (static device globals: no runtime allocation) ----
__device__ float4 g_agg[NMAX * (D / 4)];            // 25.6 MB, aggregated messages
__device__ float  g_deg[NMAX];                      // in-degree as float
__device__ float  g_Y1[(size_t)NMAX * D2];          // 51.2 MB, pre-BN layer-1 output
__device__ float  g_sum1[D2], g_sumsq1[D2];
__device__ float  g_sum2[D],  g_sumsq2[D];
__device__ float  g_scale1[D2], g_shift1[D2];
__device__ float  g_scale2[D],  g_shift2[D];

// ---------------- zero scratch ----------------------------------------------
__global__ void k_zero(int N) {
    int i      = blockIdx.x * blockDim.x + threadIdx.x;
    int stride = gridDim.x * blockDim.x;
    int na = N * (D / 4);
    float4 z = make_float4(0.f, 0.f, 0.f, 0.f);
    for (int k = i; k < na; k += stride) g_agg[k] = z;
    for (int k = i; k < N;  k += stride) g_deg[k] = 0.f;
    if (i < D2) { g_sum1[i] = 0.f; g_sumsq1[i] = 0.f; }
    if (i < D)  { g_sum2[i] = 0.f; g_sumsq2[i] = 0.f; }
}

// ---------------- edge scatter: msg = x[src] + e, agg[dst] += msg, deg[dst]++
// 16 threads per edge, one float4 chunk each. edge_feats streamed (evict-first),
// node_feats gathered (hot table, L2 resident). 16B vector RED to L2.
__global__ void k_scatter(const float4* __restrict__ nf,
                          const float4* __restrict__ ef,
                          const int*    __restrict__ src,
                          const int*    __restrict__ dst,
                          int E) {
    int gid = blockIdx.x * blockDim.x + threadIdx.x;
    if (gid >= E * 16) return;
    int e = gid >> 4;
    int c = gid & 15;
    int s = __ldg(src + e);
    int d = __ldg(dst + e);
    float4 m = __ldcs(ef + gid);               // streaming: gid == e*16 + c
    float4 n = __ldg(nf + (size_t)s * 16 + c);
    m.x += n.x; m.y += n.y; m.z += n.z; m.w += n.w;
    float4* addr = &g_agg[(size_t)d * 16 + c];
    unsigned long long ga = (unsigned long long)__cvta_generic_to_global(addr);
    asm volatile("red.global.add.v4.f32 [%0], {%1,%2,%3,%4};"
                 :: "l"(ga), "f"(m.x), "f"(m.y), "f"(m.z), "f"(m.w)
                 : "memory");
    if (c == 0) atomicAdd(&g_deg[d], 1.0f);
}

// ---------------- layer 1: h = (1+eps)*x + agg/max(deg,1); Y1 = h@W1 + b1;
// column stats accumulated. Thread j owns output column j (W1 column in regs).
__global__ void __launch_bounds__(128)
k_layer1(const float* __restrict__ nf, const float* __restrict__ epsp,
         const float* __restrict__ W1, const float* __restrict__ b1, int N) {
    __shared__ float sh[4][D];
    __shared__ float shrd[4];
    const float* aggf = (const float*)g_agg;

    int j = threadIdx.x;                 // 0..127
    float w[D];
#pragma unroll
    for (int k = 0; k < D; k++) w[k] = __ldg(W1 + k * D2 + j);
    float bj   = __ldg(b1 + j);
    float eps1 = 1.0f + __ldg(epsp);
    float ssum = 0.f, ssq = 0.f;

    int ntiles = (N + 3) >> 2;
    for (int t = blockIdx.x; t < ntiles; t += gridDim.x) {
        int i0 = t * 4;
        __syncthreads();                 // protect prev tile's sh/shrd reads
        if (threadIdx.x < 4) {
            int i = i0 + threadIdx.x;
            shrd[threadIdx.x] = (i < N) ? (1.0f / fmaxf(g_deg[i], 1.0f)) : 0.f;
        }
        __syncthreads();
        for (int l = threadIdx.x; l < 4 * D; l += 128) {
            int r = l >> 6, k = l & 63;
            int i = i0 + r;
            sh[r][k] = (i < N)
                ? eps1 * nf[(size_t)i * D + k] + aggf[(size_t)i * D + k] * shrd[r]
                : 0.f;
        }
        __syncthreads();
        float a0 = 0.f, a1 = 0.f, a2 = 0.f, a3 = 0.f;
#pragma unroll
        for (int k = 0; k < D; k++) {
            float wk = w[k];
            a0 += sh[0][k] * wk;
            a1 += sh[1][k] * wk;
            a2 += sh[2][k] * wk;
            a3 += sh[3][k] * wk;
        }
        int rem = N - i0;
        float y;
        y = a0 + bj; g_Y1[(size_t)i0 * D2 + j] = y; ssum += y; ssq += y * y;
        if (rem > 1) { y = a1 + bj; g_Y1[(size_t)(i0+1) * D2 + j] = y; ssum += y; ssq += y * y; }
        if (rem > 2) { y = a2 + bj; g_Y1[(size_t)(i0+2) * D2 + j] = y; ssum += y; ssq += y * y; }
        if (rem > 3) { y = a3 + bj; g_Y1[(size_t)(i0+3) * D2 + j] = y; ssum += y; ssq += y * y; }
    }
    atomicAdd(&g_sum1[j],   ssum);
    atomicAdd(&g_sumsq1[j], ssq);
}

// ---------------- BN finalize: scale/shift from (sum, sumsq) ----------------
__global__ void k_stats1(const float* __restrict__ gamma,
                         const float* __restrict__ beta, float invN) {
    int j = threadIdx.x;
    float m  = g_sum1[j] * invN;
    float v  = g_sumsq1[j] * invN - m * m;
    float sc = gamma[j] * rsqrtf(v + 1e-5f);
    g_scale1[j] = sc;
    g_shift1[j] = beta[j] - m * sc;
}

__global__ void k_stats2(const float* __restrict__ gamma,
                         const float* __restrict__ beta, float invN) {
    int j = threadIdx.x;
    float m  = g_sum2[j] * invN;
    float v  = g_sumsq2[j] * invN - m * m;
    float sc = gamma[j] * rsqrtf(v + 1e-5f);
    g_scale2[j] = sc;
    g_shift2[j] = beta[j] - m * sc;
}

// ---------------- layer 2: x1 = relu(BN(Y1)); Y2 = x1@W2 + b2 (-> d_out);
// split-K: half 0/1 each own 64 of the 128 K-values, combine via shared.
__global__ void __launch_bounds__(128)
k_layer2(const float* __restrict__ W2, const float* __restrict__ b2,
         float* __restrict__ out, int N) {
    __shared__ float sx[2][D2];
    __shared__ float spart[2][D];
    __shared__ float ssc[D2], ssh[D2];

    int t = threadIdx.x;
    int j = t & 63, half = t >> 6;
    float w[64];
#pragma unroll
    for (int k = 0; k < 64; k++) w[k] = __ldg(W2 + (size_t)(half * 64 + k) * D + j);
    float bj = __ldg(b2 + j);
    ssc[t] = g_scale1[t];
    ssh[t] = g_shift1[t];
    float ssum = 0.f, ssq = 0.f;

    int ntiles = (N + 1) >> 1;
    __syncthreads();
    for (int tt = blockIdx.x; tt < ntiles; tt += gridDim.x) {
        int i0 = tt * 2;
        __syncthreads();                 // protect prev tile's sx/spart reads
        for (int l = t; l < 2 * D2; l += 128) {
            int r = l >> 7, k = l & 127;
            int i = i0 + r;
            float x = 0.f;
            if (i < N) {
                float y = g_Y1[(size_t)i * D2 + k];
                x = fmaxf(y * ssc[k] + ssh[k], 0.f);
            }
            sx[r][k] = x;
        }
        __syncthreads();
        float a0 = 0.f, a1 = 0.f;
        const int kb = half * 64;
#pragma unroll
        for (int k = 0; k < 64; k++) {
            float wk = w[k];
            a0 += sx[0][kb + k] * wk;
            a1 += sx[1][kb + k] * wk;
        }
        if (half == 1) { spart[0][j] = a0; spart[1][j] = a1; }
        __syncthreads();
        if (half == 0) {
            float y0 = a0 + spart[0][j] + bj;
            out[(size_t)i0 * D + j] = y0; ssum += y0; ssq += y0 * y0;
            if (i0 + 1 < N) {
                float y1 = a1 + spart[1][j] + bj;
                out[(size_t)(i0 + 1) * D + j] = y1; ssum += y1; ssq += y1 * y1;
            }
        }
    }
    if (half == 0) {
        atomicAdd(&g_sum2[j],   ssum);
        atomicAdd(&g_sumsq2[j], ssq);
    }
}

// ---------------- final BN+ReLU in place on d_out (float4) ------------------
__global__ void k_bnrelu2(float4* __restrict__ out, int total4) {
    int i = blockIdx.x * blockDim.x + threadIdx.x;
    if (i >= total4) return;
    int j0 = (i & 15) * 4;
    float4 v = out[i];
    v.x = fmaxf(v.x * g_scale2[j0 + 0] + g_shift2[j0 + 0], 0.f);
    v.y = fmaxf(v.y * g_scale2[j0 + 1] + g_shift2[j0 + 1], 0.f);
    v.z = fmaxf(v.z * g_scale2[j0 + 2] + g_shift2[j0 + 2], 0.f);
    v.w = fmaxf(v.w * g_scale2[j0 + 3] + g_shift2[j0 + 3], 0.f);
    out[i] = v;
}

// ---------------- launcher ---------------------------------------------------
extern "C" void kernel_launch(void* const* d_in, const int* in_sizes, int n_in,
                              void* d_out, int out_size) {
    const float* node   = (const float*)d_in[0];
    const float* edge   = (const float*)d_in[1];
    const int*   src    = (const int*)  d_in[2];
    const int*   dst    = (const int*)  d_in[3];
    const float* eps    = (const float*)d_in[4];
    const float* W1     = (const float*)d_in[5];
    const float* b1     = (const float*)d_in[6];
    const float* gamma1 = (const float*)d_in[7];
    const float* beta1  = (const float*)d_in[8];
    const float* W2     = (const float*)d_in[9];
    const float* b2     = (const float*)d_in[10];
    const float* gamma2 = (const float*)d_in[11];
    const float* beta2  = (const float*)d_in[12];

    int N = in_sizes[0] / D;
    int E = in_sizes[2];
    float* out = (float*)d_out;
    float invN = 1.0f / (float)N;

    k_zero<<<1184, 256>>>(N);

    int nthr = E * 16;
    k_scatter<<<(nthr + 255) / 256, 256>>>((const float4*)node,
                                           (const float4*)edge, src, dst, E);

    k_layer1<<<888, 128>>>(node, eps, W1, b1, N);
    k_stats1<<<1, 128>>>(gamma1, beta1, invN);
    k_layer2<<<888, 128>>>(W2, b2, out, N);
    k_stats2<<<1, 64>>>(gamma2, beta2, invN);
    k_bnrelu2<<<(N * 16 + 255) / 256, 256>>>((float4*)out, N * 16);
}

// round 10
// speedup vs baseline: 1.3339x; 1.3339x over previous
#include <cuda_runtime.h>
#include <cstdint>

// Problem constants (fixed by the dataset: N=100000, E=1600000, D=64)
#define NMAX   100000
#define D      64
#define D2     128
#define BINCAP 128     // max degree capacity; E/N=16 avg (Poisson), P(deg>128) ~ 0

// ---------------- scratch (static device globals) ---------------------------
__device__ int    g_cnt[NMAX];                       // per-node in-degree / slot counter
__device__ int    g_bins[(size_t)NMAX * BINCAP];     // 51.2 MB, edge ids bucketed by dst
__device__ float  g_H[(size_t)NMAX * D];             // 25.6 MB, combined input h
__device__ float  g_Y1[(size_t)NMAX * D2];           // 51.2 MB, pre-BN layer-1 output
__device__ float  g_sum1[D2], g_sumsq1[D2];
__device__ float  g_sum2[D],  g_sumsq2[D];
__device__ float  g_scale1[D2], g_shift1[D2];
__device__ float  g_scale2[D],  g_shift2[D];

// ---------------- zero counters + stats --------------------------------------
__global__ void k_zero(int N) {
    int i      = blockIdx.x * blockDim.x + threadIdx.x;
    int stride = gridDim.x * blockDim.x;
    for (int k = i; k < N; k += stride) g_cnt[k] = 0;
    if (i < D2) { g_sum1[i] = 0.f; g_sumsq1[i] = 0.f; }
    if (i < D)  { g_sum2[i] = 0.f; g_sumsq2[i] = 0.f; }
}

// ---------------- bin edges by destination -----------------------------------
__global__ void k_place(const int* __restrict__ dst, int E) {
    int e = blockIdx.x * blockDim.x + threadIdx.x;
    if (e >= E) return;
    int d = __ldg(dst + e);
    int slot = atomicAdd(&g_cnt[d], 1);
    if (slot < BINCAP) g_bins[(size_t)d * BINCAP + slot] = e;
}

// ---------------- gather aggregation: one warp per node ----------------------
// h[n] = (1+eps)*x[n] + (sum_{e: dst=n} (x[src_e] + ef_e)) / max(deg,1)
// Lane l owns float2 chunk l (64 floats = 32 float2 per row).
__global__ void __launch_bounds__(256)
k_gather(const float2* __restrict__ nf2, const float2* __restrict__ ef2,
         const int* __restrict__ src, const float* __restrict__ epsp, int N) {
    int n    = (blockIdx.x * blockDim.x + threadIdx.x) >> 5;
    int lane = threadIdx.x & 31;
    if (n >= N) return;

    int degc = g_cnt[n];
    int deg  = min(degc, BINCAP);
    float2 acc = make_float2(0.f, 0.f);

    for (int base = 0; base < deg; base += 32) {
        int m = min(32, deg - base);
        int eid = 0, s = 0;
        if (lane < m) {
            eid = g_bins[(size_t)n * BINCAP + base + lane];
            s   = __ldg(src + eid);
        }
#pragma unroll 4
        for (int i = 0; i < m; i++) {
            int e  = __shfl_sync(0xffffffffu, eid, i);
            int ss = __shfl_sync(0xffffffffu, s,   i);
            float2 ev = __ldcs(ef2 + (size_t)e  * 32 + lane);  // streamed, evict-first
            float2 nv = __ldg (nf2 + (size_t)ss * 32 + lane);  // hot table, L2
            acc.x += ev.x + nv.x;
            acc.y += ev.y + nv.y;
        }
    }
    float inv  = 1.0f / fmaxf((float)degc, 1.0f);
    float eps1 = 1.0f + __ldg(epsp);
    float2 x = __ldg(nf2 + (size_t)n * 32 + lane);
    float2 h;
    h.x = eps1 * x.x + acc.x * inv;
    h.y = eps1 * x.y + acc.y * inv;
    ((float2*)g_H)[(size_t)n * 32 + lane] = h;
}

// ---------------- packed-f32x2 helpers ---------------------------------------
__device__ __forceinline__ unsigned long long pack_dup(float a) {
    unsigned long long r;
    asm("mov.b64 %0, {%1,%1};" : "=l"(r) : "f"(a));
    return r;
}
__device__ __forceinline__ void fma2(unsigned long long& acc,
                                     unsigned long long a, unsigned long long b) {
    asm("fma.rn.f32x2 %0, %1, %2, %0;" : "+l"(acc) : "l"(a), "l"(b));
}
__device__ __forceinline__ void unpack2(unsigned long long v, float& lo, float& hi) {
    asm("mov.b64 {%0,%1}, %2;" : "=f"(lo), "=f"(hi) : "l"(v));
}

// ---------------- layer 1: Y1 = h@W1 + b1 (+ column stats) -------------------
// 128 threads, thread j owns output column j. 8-row tiles, rows packed in pairs.
__global__ void __launch_bounds__(128)
k_layer1(const float* __restrict__ W1, const float* __restrict__ b1, int N) {
    __shared__ float2 sh2[4 * D];        // [pair p][k]: {h[2p][k], h[2p+1][k]}

    int j = threadIdx.x;
    float w[D];
#pragma unroll
    for (int k = 0; k < D; k++) w[k] = __ldg(W1 + k * D2 + j);
    float bj = __ldg(b1 + j);
    float ssum = 0.f, ssq = 0.f;

    int ntiles = (N + 7) >> 3;
    for (int t = blockIdx.x; t < ntiles; t += gridDim.x) {
        int i0 = t * 8;
        __syncthreads();                 // protect prev tile's reads
        // stage: thread j -> rows 2m+(j>>6), col j&63, m=0..3
#pragma unroll
        for (int m = 0; m < 4; m++) {
            int r = 2 * m + (j >> 6);
            int k = j & 63;
            int i = i0 + r;
            float v = (i < N) ? g_H[(size_t)i * D + k] : 0.f;
            if (j >> 6) sh2[m * D + k].y = v; else sh2[m * D + k].x = v;
        }
        __syncthreads();
        unsigned long long a0 = 0, a1 = 0, a2 = 0, a3 = 0;
#pragma unroll
        for (int k = 0; k < D; k++) {
            unsigned long long wp = pack_dup(w[k]);
            unsigned long long s0 = *(const unsigned long long*)&sh2[0 * D + k];
            unsigned long long s1 = *(const unsigned long long*)&sh2[1 * D + k];
            unsigned long long s2 = *(const unsigned long long*)&sh2[2 * D + k];
            unsigned long long s3 = *(const unsigned long long*)&sh2[3 * D + k];
            fma2(a0, s0, wp);
            fma2(a1, s1, wp);
            fma2(a2, s2, wp);
            fma2(a3, s3, wp);
        }
        float y[8];
        unpack2(a0, y[0], y[1]);
        unpack2(a1, y[2], y[3]);
        unpack2(a2, y[4], y[5]);
        unpack2(a3, y[6], y[7]);
        int rem = N - i0;
#pragma unroll
        for (int r = 0; r < 8; r++) {
            if (r < rem) {
                float yy = y[r] + bj;
                g_Y1[(size_t)(i0 + r) * D2 + j] = yy;
                ssum += yy; ssq += yy * yy;
            }
        }
    }
    atomicAdd(&g_sum1[j],   ssum);
    atomicAdd(&g_sumsq1[j], ssq);
}

// ---------------- BN finalize ------------------------------------------------
__global__ void k_stats1(const float* __restrict__ gamma,
                         const float* __restrict__ beta, float invN) {
    int j = threadIdx.x;
    float m  = g_sum1[j] * invN;
    float v  = g_sumsq1[j] * invN - m * m;
    float sc = gamma[j] * rsqrtf(v + 1e-5f);
    g_scale1[j] = sc;
    g_shift1[j] = beta[j] - m * sc;
}
__global__ void k_stats2(const float* __restrict__ gamma,
                         const float* __restrict__ beta, float invN) {
    int j = threadIdx.x;
    float m  = g_sum2[j] * invN;
    float v  = g_sumsq2[j] * invN - m * m;
    float sc = gamma[j] * rsqrtf(v + 1e-5f);
    g_scale2[j] = sc;
    g_shift2[j] = beta[j] - m * sc;
}

// ---------------- layer 2: x1 = relu(BN(Y1)); Y2 = x1@W2 + b2 -> d_out -------
// split-K across halves (64 k each), 8-row tiles, rows packed in pairs.
__global__ void __launch_bounds__(128)
k_layer2(const float* __restrict__ W2, const float* __restrict__ b2,
         float* __restrict__ out, int N) {
    __shared__ float2 sx2[4 * D2];                 // [pair p][k 0..127]
    __shared__ unsigned long long sp[4 * D];       // half-1 partials [p][j]
    __shared__ float ssc[D2], ssh[D2];

    int t = threadIdx.x;
    int j = t & 63, half = t >> 6;
    float w[64];
#pragma unroll
    for (int k = 0; k < 64; k++) w[k] = __ldg(W2 + (size_t)(half * 64 + k) * D + j);
    float bj = __ldg(b2 + j);
    ssc[t] = g_scale1[t];
    ssh[t] = g_shift1[t];
    float ssum = 0.f, ssq = 0.f;

    int ntiles = (N + 7) >> 3;
    __syncthreads();
    for (int tt = blockIdx.x; tt < ntiles; tt += gridDim.x) {
        int i0 = tt * 8;
        __syncthreads();                 // protect prev tile's reads
        // stage: thread t owns column k=t, 8 rows (uniform per-m branch)
#pragma unroll
        for (int m = 0; m < 8; m++) {
            int i = i0 + m;
            float v = 0.f;
            if (i < N) {
                float y = g_Y1[(size_t)i * D2 + t];
                v = fmaxf(y * ssc[t] + ssh[t], 0.f);
            }
            if (m & 1) sx2[(m >> 1) * D2 + t].y = v;
            else       sx2[(m >> 1) * D2 + t].x = v;
        }
        __syncthreads();
        unsigned long long a0 = 0, a1 = 0, a2 = 0, a3 = 0;
        const int kb = half * 64;
#pragma unroll
        for (int k = 0; k < 64; k++) {
            unsigned long long wp = pack_dup(w[k]);
            unsigned long long s0 = *(const unsigned long long*)&sx2[0 * D2 + kb + k];
            unsigned long long s1 = *(const unsigned long long*)&sx2[1 * D2 + kb + k];
            unsigned long long s2 = *(const unsigned long long*)&sx2[2 * D2 + kb + k];
            unsigned long long s3 = *(const unsigned long long*)&sx2[3 * D2 + kb + k];
            fma2(a0, s0, wp);
            fma2(a1, s1, wp);
            fma2(a2, s2, wp);
            fma2(a3, s3, wp);
        }
        if (half == 1) {
            sp[0 * D + j] = a0; sp[1 * D + j] = a1;
            sp[2 * D + j] = a2; sp[3 * D + j] = a3;
        }
        __syncthreads();
        if (half == 0) {
            int rem = N - i0;
            unsigned long long mine[4] = {a0, a1, a2, a3};
#pragma unroll
            for (int p = 0; p < 4; p++) {
                float alo, ahi, blo, bhi;
                unpack2(mine[p], alo, ahi);
                unpack2(sp[p * D + j], blo, bhi);
                int r0 = 2 * p, r1 = 2 * p + 1;
                if (r0 < rem) {
                    float y0 = alo + blo + bj;
                    out[(size_t)(i0 + r0) * D + j] = y0;
                    ssum += y0; ssq += y0 * y0;
                }
                if (r1 < rem) {
                    float y1 = ahi + bhi + bj;
                    out[(size_t)(i0 + r1) * D + j] = y1;
                    ssum += y1; ssq += y1 * y1;
                }
            }
        }
    }
    if (half == 0) {
        atomicAdd(&g_sum2[j],   ssum);
        atomicAdd(&g_sumsq2[j], ssq);
    }
}

// ---------------- final BN+ReLU in place on d_out (float4) -------------------
__global__ void k_bnrelu2(float4* __restrict__ out, int total4) {
    int i = blockIdx.x * blockDim.x + threadIdx.x;
    if (i >= total4) return;
    int j0 = (i & 15) * 4;
    float4 v = out[i];
    v.x = fmaxf(v.x * g_scale2[j0 + 0] + g_shift2[j0 + 0], 0.f);
    v.y = fmaxf(v.y * g_scale2[j0 + 1] + g_shift2[j0 + 1], 0.f);
    v.z = fmaxf(v.z * g_scale2[j0 + 2] + g_shift2[j0 + 2], 0.f);
    v.w = fmaxf(v.w * g_scale2[j0 + 3] + g_shift2[j0 + 3], 0.f);
    out[i] = v;
}

// ---------------- launcher ---------------------------------------------------
extern "C" void kernel_launch(void* const* d_in, const int* in_sizes, int n_in,
                              void* d_out, int out_size) {
    const float* node   = (const float*)d_in[0];
    const float* edge   = (const float*)d_in[1];
    const int*   src    = (const int*)  d_in[2];
    const int*   dst    = (const int*)  d_in[3];
    const float* eps    = (const float*)d_in[4];
    const float* W1     = (const float*)d_in[5];
    const float* b1     = (const float*)d_in[6];
    const float* gamma1 = (const float*)d_in[7];
    const float* beta1  = (const float*)d_in[8];
    const float* W2     = (const float*)d_in[9];
    const float* b2     = (const float*)d_in[10];
    const float* gamma2 = (const float*)d_in[11];
    const float* beta2  = (const float*)d_in[12];

    int N = in_sizes[0] / D;
    int E = in_sizes[2];
    float* out = (float*)d_out;
    float invN = 1.0f / (float)N;

    k_zero<<<416, 256>>>(N);
    k_place<<<(E + 255) / 256, 256>>>(dst, E);
    k_gather<<<(N + 7) / 8, 256>>>((const float2*)node, (const float2*)edge,
                                   src, eps, N);
    k_layer1<<<1184, 128>>>(W1, b1, N);
    k_stats1<<<1, 128>>>(gamma1, beta1, invN);
    k_layer2<<<1184, 128>>>(W2, b2, out, N);
    k_stats2<<<1, 64>>>(gamma2, beta2, invN);
    k_bnrelu2<<<(N * 16 + 255) / 256, 256>>>((float4*)out, N * 16);
}

// round 11
// speedup vs baseline: 1.3410x; 1.0054x over previous
#include <cuda_runtime.h>
#include <cstdint>

// Problem constants (fixed by the dataset: N=100000, E=1600000, D=64)
#define NMAX   100000
#define D      64
#define D2     128
#define BINCAP 128     // max degree capacity; E/N=16 avg (Poisson), P(deg>128) ~ 0

// ---------------- scratch (static device globals) ---------------------------
__device__ int    g_cnt[NMAX];                       // per-node in-degree / slot counter
__device__ int    g_bins[(size_t)NMAX * BINCAP];     // 51.2 MB, edge ids bucketed by dst
__device__ float  g_H[(size_t)NMAX * D];             // 25.6 MB, combined input h
__device__ float  g_Y1[(size_t)NMAX * D2];           // 51.2 MB, pre-BN layer-1 output
__device__ float  g_sum1[D2], g_sumsq1[D2];
__device__ float  g_sum2[D],  g_sumsq2[D];
__device__ float  g_scale1[D2], g_shift1[D2];
__device__ float  g_scale2[D],  g_shift2[D];

// ---------------- zero counters + stats --------------------------------------
__global__ void k_zero(int N) {
    int i      = blockIdx.x * blockDim.x + threadIdx.x;
    int stride = gridDim.x * blockDim.x;
    for (int k = i; k < N; k += stride) g_cnt[k] = 0;
    if (i < D2) { g_sum1[i] = 0.f; g_sumsq1[i] = 0.f; }
    if (i < D)  { g_sum2[i] = 0.f; g_sumsq2[i] = 0.f; }
}

// ---------------- bin edges by destination -----------------------------------
__global__ void k_place(const int* __restrict__ dst, int E) {
    int e = blockIdx.x * blockDim.x + threadIdx.x;
    if (e >= E) return;
    int d = __ldg(dst + e);
    int slot = atomicAdd(&g_cnt[d], 1);
    if (slot < BINCAP) g_bins[(size_t)d * BINCAP + slot] = e;
}

// ---------------- gather aggregation: one warp per node ----------------------
// h[n] = (1+eps)*x[n] + (sum_{e: dst=n} (x[src_e] + ef_e)) / max(deg,1)
// Lane l owns float2 chunk l (64 floats = 32 float2 per row).
__global__ void __launch_bounds__(256)
k_gather(const float2* __restrict__ nf2, const float2* __restrict__ ef2,
         const int* __restrict__ src, const float* __restrict__ epsp, int N) {
    int n    = (blockIdx.x * blockDim.x + threadIdx.x) >> 5;
    int lane = threadIdx.x & 31;
    if (n >= N) return;

    int degc = g_cnt[n];
    int deg  = min(degc, BINCAP);
    float2 acc = make_float2(0.f, 0.f);

    for (int base = 0; base < deg; base += 32) {
        int m = min(32, deg - base);
        int eid = 0, s = 0;
        if (lane < m) {
            eid = g_bins[(size_t)n * BINCAP + base + lane];
            s   = __ldg(src + eid);
        }
#pragma unroll 4
        for (int i = 0; i < m; i++) {
            int e  = __shfl_sync(0xffffffffu, eid, i);
            int ss = __shfl_sync(0xffffffffu, s,   i);
            float2 ev = __ldcs(ef2 + (size_t)e  * 32 + lane);  // streamed, evict-first
            float2 nv = __ldg (nf2 + (size_t)ss * 32 + lane);  // hot table, L2
            acc.x += ev.x + nv.x;
            acc.y += ev.y + nv.y;
        }
    }
    float inv  = 1.0f / fmaxf((float)degc, 1.0f);
    float eps1 = 1.0f + __ldg(epsp);
    float2 x = __ldg(nf2 + (size_t)n * 32 + lane);
    float2 h;
    h.x = eps1 * x.x + acc.x * inv;
    h.y = eps1 * x.y + acc.y * inv;
    ((float2*)g_H)[(size_t)n * 32 + lane] = h;
}

// ---------------- packed-f32x2 helpers ---------------------------------------
__device__ __forceinline__ unsigned long long pack_dup(float a) {
    unsigned long long r;
    asm("mov.b64 %0, {%1,%1};" : "=l"(r) : "f"(a));
    return r;
}
__device__ __forceinline__ void fma2(unsigned long long& acc,
                                     unsigned long long a, unsigned long long b) {
    asm("fma.rn.f32x2 %0, %1, %2, %0;" : "+l"(acc) : "l"(a), "l"(b));
}
__device__ __forceinline__ void unpack2(unsigned long long v, float& lo, float& hi) {
    asm("mov.b64 {%0,%1}, %2;" : "=f"(lo), "=f"(hi) : "l"(v));
}

// ---------------- layer 1: Y1 = h@W1 + b1 (+ column stats) -------------------
// 128 threads, thread j owns output column j. 8-row tiles, rows packed in pairs.
__global__ void __launch_bounds__(128)
k_layer1(const float* __restrict__ W1, const float* __restrict__ b1, int N) {
    __shared__ float2 sh2[4 * D];        // [pair p][k]: {h[2p][k], h[2p+1][k]}

    int j = threadIdx.x;
    float w[D];
#pragma unroll
    for (int k = 0; k < D; k++) w[k] = __ldg(W1 + k * D2 + j);
    float bj = __ldg(b1 + j);
    float ssum = 0.f, ssq = 0.f;

    int ntiles = (N + 7) >> 3;
    for (int t = blockIdx.x; t < ntiles; t += gridDim.x) {
        int i0 = t * 8;
        __syncthreads();                 // protect prev tile's reads
        // stage: thread j -> rows 2m+(j>>6), col j&63, m=0..3
#pragma unroll
        for (int m = 0; m < 4; m++) {
            int r = 2 * m + (j >> 6);
            int k = j & 63;
            int i = i0 + r;
            float v = (i < N) ? g_H[(size_t)i * D + k] : 0.f;
            if (j >> 6) sh2[m * D + k].y = v; else sh2[m * D + k].x = v;
        }
        __syncthreads();
        unsigned long long a0 = 0, a1 = 0, a2 = 0, a3 = 0;
#pragma unroll
        for (int k = 0; k < D; k++) {
            unsigned long long wp = pack_dup(w[k]);
            unsigned long long s0 = *(const unsigned long long*)&sh2[0 * D + k];
            unsigned long long s1 = *(const unsigned long long*)&sh2[1 * D + k];
            unsigned long long s2 = *(const unsigned long long*)&sh2[2 * D + k];
            unsigned long long s3 = *(const unsigned long long*)&sh2[3 * D + k];
            fma2(a0, s0, wp);
            fma2(a1, s1, wp);
            fma2(a2, s2, wp);
            fma2(a3, s3, wp);
        }
        float y[8];
        unpack2(a0, y[0], y[1]);
        unpack2(a1, y[2], y[3]);
        unpack2(a2, y[4], y[5]);
        unpack2(a3, y[6], y[7]);
        int rem = N - i0;
#pragma unroll
        for (int r = 0; r < 8; r++) {
            if (r < rem) {
                float yy = y[r] + bj;
                g_Y1[(size_t)(i0 + r) * D2 + j] = yy;
                ssum += yy; ssq += yy * yy;
            }
        }
    }
    atomicAdd(&g_sum1[j],   ssum);
    atomicAdd(&g_sumsq1[j], ssq);
}

// ---------------- BN finalize ------------------------------------------------
__global__ void k_stats1(const float* __restrict__ gamma,
                         const float* __restrict__ beta, float invN) {
    int j = threadIdx.x;
    float m  = g_sum1[j] * invN;
    float v  = g_sumsq1[j] * invN - m * m;
    float sc = gamma[j] * rsqrtf(v + 1e-5f);
    g_scale1[j] = sc;
    g_shift1[j] = beta[j] - m * sc;
}
__global__ void k_stats2(const float* __restrict__ gamma,
                         const float* __restrict__ beta, float invN) {
    int j = threadIdx.x;
    float m  = g_sum2[j] * invN;
    float v  = g_sumsq2[j] * invN - m * m;
    float sc = gamma[j] * rsqrtf(v + 1e-5f);
    g_scale2[j] = sc;
    g_shift2[j] = beta[j] - m * sc;
}

// ---------------- layer 2: x1 = relu(BN(Y1)); Y2 = x1@W2 + b2 -> d_out -------
// split-K across halves (64 k each), 8-row tiles, rows packed in pairs.
__global__ void __launch_bounds__(128)
k_layer2(const float* __restrict__ W2, const float* __restrict__ b2,
         float* __restrict__ out, int N) {
    __shared__ float2 sx2[4 * D2];                 // [pair p][k 0..127]
    __shared__ unsigned long long sp[4 * D];       // half-1 partials [p][j]
    __shared__ float ssc[D2], ssh[D2];

    int t = threadIdx.x;
    int j = t & 63, half = t >> 6;
    float w[64];
#pragma unroll
    for (int k = 0; k < 64; k++) w[k] = __ldg(W2 + (size_t)(half * 64 + k) * D + j);
    float bj = __ldg(b2 + j);
    ssc[t] = g_scale1[t];
    ssh[t] = g_shift1[t];
    float ssum = 0.f, ssq = 0.f;

    int ntiles = (N + 7) >> 3;
    __syncthreads();
    for (int tt = blockIdx.x; tt < ntiles; tt += gridDim.x) {
        int i0 = tt * 8;
        __syncthreads();                 // protect prev tile's reads
        // stage: thread t owns column k=t, 8 rows (uniform per-m branch)
#pragma unroll
        for (int m = 0; m < 8; m++) {
            int i = i0 + m;
            float v = 0.f;
            if (i < N) {
                float y = g_Y1[(size_t)i * D2 + t];
                v = fmaxf(y * ssc[t] + ssh[t], 0.f);
            }
            if (m & 1) sx2[(m >> 1) * D2 + t].y = v;
            else       sx2[(m >> 1) * D2 + t].x = v;
        }
        __syncthreads();
        unsigned long long a0 = 0, a1 = 0, a2 = 0, a3 = 0;
        const int kb = half * 64;
#pragma unroll
        for (int k = 0; k < 64; k++) {
            unsigned long long wp = pack_dup(w[k]);
            unsigned long long s0 = *(const unsigned long long*)&sx2[0 * D2 + kb + k];
            unsigned long long s1 = *(const unsigned long long*)&sx2[1 * D2 + kb + k];
            unsigned long long s2 = *(const unsigned long long*)&sx2[2 * D2 + kb + k];
            unsigned long long s3 = *(const unsigned long long*)&sx2[3 * D2 + kb + k];
            fma2(a0, s0, wp);
            fma2(a1, s1, wp);
            fma2(a2, s2, wp);
            fma2(a3, s3, wp);
        }
        if (half == 1) {
            sp[0 * D + j] = a0; sp[1 * D + j] = a1;
            sp[2 * D + j] = a2; sp[3 * D + j] = a3;
        }
        __syncthreads();
        if (half == 0) {
            int rem = N - i0;
            unsigned long long mine[4] = {a0, a1, a2, a3};
#pragma unroll
            for (int p = 0; p < 4; p++) {
                float alo, ahi, blo, bhi;
                unpack2(mine[p], alo, ahi);
                unpack2(sp[p * D + j], blo, bhi);
                int r0 = 2 * p, r1 = 2 * p + 1;
                if (r0 < rem) {
                    float y0 = alo + blo + bj;
                    out[(size_t)(i0 + r0) * D + j] = y0;
                    ssum += y0; ssq += y0 * y0;
                }
                if (r1 < rem) {
                    float y1 = ahi + bhi + bj;
                    out[(size_t)(i0 + r1) * D + j] = y1;
                    ssum += y1; ssq += y1 * y1;
                }
            }
        }
    }
    if (half == 0) {
        atomicAdd(&g_sum2[j],   ssum);
        atomicAdd(&g_sumsq2[j], ssq);
    }
}

// ---------------- final BN+ReLU in place on d_out (float4) -------------------
__global__ void k_bnrelu2(float4* __restrict__ out, int total4) {
    int i = blockIdx.x * blockDim.x + threadIdx.x;
    if (i >= total4) return;
    int j0 = (i & 15) * 4;
    float4 v = out[i];
    v.x = fmaxf(v.x * g_scale2[j0 + 0] + g_shift2[j0 + 0], 0.f);
    v.y = fmaxf(v.y * g_scale2[j0 + 1] + g_shift2[j0 + 1], 0.f);
    v.z = fmaxf(v.z * g_scale2[j0 + 2] + g_shift2[j0 + 2], 0.f);
    v.w = fmaxf(v.w * g_scale2[j0 + 3] + g_shift2[j0 + 3], 0.f);
    out[i] = v;
}

// ---------------- launcher ---------------------------------------------------
extern "C" void kernel_launch(void* const* d_in, const int* in_sizes, int n_in,
                              void* d_out, int out_size) {
    const float* node   = (const float*)d_in[0];
    const float* edge   = (const float*)d_in[1];
    const int*   src    = (const int*)  d_in[2];
    const int*   dst    = (const int*)  d_in[3];
    const float* eps    = (const float*)d_in[4];
    const float* W1     = (const float*)d_in[5];
    const float* b1     = (const float*)d_in[6];
    const float* gamma1 = (const float*)d_in[7];
    const float* beta1  = (const float*)d_in[8];
    const float* W2     = (const float*)d_in[9];
    const float* b2     = (const float*)d_in[10];
    const float* gamma2 = (const float*)d_in[11];
    const float* beta2  = (const float*)d_in[12];

    int N = in_sizes[0] / D;
    int E = in_sizes[2];
    float* out = (float*)d_out;
    float invN = 1.0f / (float)N;

    k_zero<<<416, 256>>>(N);
    k_place<<<(E + 255) / 256, 256>>>(dst, E);
    k_gather<<<(N + 7) / 8, 256>>>((const float2*)node, (const float2*)edge,
                                   src, eps, N);
    k_layer1<<<1184, 128>>>(W1, b1, N);
    k_stats1<<<1, 128>>>(gamma1, beta1, invN);
    k_layer2<<<1184, 128>>>(W2, b2, out, N);
    k_stats2<<<1, 64>>>(gamma2, beta2, invN);
    k_bnrelu2<<<(N * 16 + 255) / 256, 256>>>((float4*)out, N * 16);
}

// round 12
// speedup vs baseline: 1.3527x; 1.0087x over previous
#include <cuda_runtime.h>
#include <cstdint>

// Problem constants (fixed by the dataset: N=100000, E=1600000, D=64)
#define NMAX   100000
#define D      64
#define D2     128
#define BINCAP 128     // max degree capacity; E/N=16 avg (Poisson), P(deg>128) ~ 0

// ---------------- scratch (static device globals) ---------------------------
__device__ int    g_cnt[NMAX];                       // per-node in-degree / slot counter
__device__ int    g_bins[(size_t)NMAX * BINCAP];     // 51.2 MB, edge ids bucketed by dst
__device__ float  g_H[(size_t)NMAX * D];             // 25.6 MB, combined input h
__device__ float  g_Y1[(size_t)NMAX * D2];           // 51.2 MB, pre-BN layer-1 output
__device__ float  g_sum1[D2], g_sumsq1[D2];
__device__ float  g_sum2[D],  g_sumsq2[D];
__device__ float  g_scale1[D2], g_shift1[D2];
__device__ float  g_scale2[D],  g_shift2[D];

// ---------------- zero counters + stats --------------------------------------
__global__ void k_zero(int N) {
    int i      = blockIdx.x * blockDim.x + threadIdx.x;
    int stride = gridDim.x * blockDim.x;
    for (int k = i; k < N; k += stride) g_cnt[k] = 0;
    if (i < D2) { g_sum1[i] = 0.f; g_sumsq1[i] = 0.f; }
    if (i < D)  { g_sum2[i] = 0.f; g_sumsq2[i] = 0.f; }
}

// ---------------- bin edges by destination -----------------------------------
__global__ void k_place(const int* __restrict__ dst, int E) {
    int e = blockIdx.x * blockDim.x + threadIdx.x;
    if (e >= E) return;
    int d = __ldg(dst + e);
    int slot = atomicAdd(&g_cnt[d], 1);
    if (slot < BINCAP) g_bins[(size_t)d * BINCAP + slot] = e;
}

// ---------------- gather aggregation: one warp per node ----------------------
// h[n] = (1+eps)*x[n] + (sum_{e: dst=n} (x[src_e] + ef_e)) / max(deg,1)
// Lane l owns float2 chunk l (64 floats = 32 float2 per row).
__global__ void __launch_bounds__(256)
k_gather(const float2* __restrict__ nf2, const float2* __restrict__ ef2,
         const int* __restrict__ src, const float* __restrict__ epsp, int N) {
    int n    = (blockIdx.x * blockDim.x + threadIdx.x) >> 5;
    int lane = threadIdx.x & 31;
    if (n >= N) return;

    int degc = g_cnt[n];
    int deg  = min(degc, BINCAP);
    float2 acc = make_float2(0.f, 0.f);

    for (int base = 0; base < deg; base += 32) {
        int m = min(32, deg - base);
        int eid = 0, s = 0;
        if (lane < m) {
            eid = g_bins[(size_t)n * BINCAP + base + lane];
            s   = __ldg(src + eid);
        }
#pragma unroll 4
        for (int i = 0; i < m; i++) {
            int e  = __shfl_sync(0xffffffffu, eid, i);
            int ss = __shfl_sync(0xffffffffu, s,   i);
            float2 ev = __ldcs(ef2 + (size_t)e  * 32 + lane);  // streamed, evict-first
            float2 nv = __ldg (nf2 + (size_t)ss * 32 + lane);  // hot table, L2
            acc.x += ev.x + nv.x;
            acc.y += ev.y + nv.y;
        }
    }
    float inv  = 1.0f / fmaxf((float)degc, 1.0f);
    float eps1 = 1.0f + __ldg(epsp);
    float2 x = __ldg(nf2 + (size_t)n * 32 + lane);
    float2 h;
    h.x = eps1 * x.x + acc.x * inv;
    h.y = eps1 * x.y + acc.y * inv;
    ((float2*)g_H)[(size_t)n * 32 + lane] = h;
}

// ---------------- packed-f32x2 helpers ---------------------------------------
__device__ __forceinline__ unsigned long long pack_dup(float a) {
    unsigned long long r;
    asm("mov.b64 %0, {%1,%1};" : "=l"(r) : "f"(a));
    return r;
}
__device__ __forceinline__ void fma2(unsigned long long& acc,
                                     unsigned long long a, unsigned long long b) {
    asm("fma.rn.f32x2 %0, %1, %2, %0;" : "+l"(acc) : "l"(a), "l"(b));
}
__device__ __forceinline__ void unpack2(unsigned long long v, float& lo, float& hi) {
    asm("mov.b64 {%0,%1}, %2;" : "=f"(lo), "=f"(hi) : "l"(v));
}

// ---------------- layer 1: Y1 = h@W1 + b1 (+ column stats) -------------------
// 128 threads, thread j owns output column j. 8-row tiles, rows packed in pairs.
__global__ void __launch_bounds__(128)
k_layer1(const float* __restrict__ W1, const float* __restrict__ b1, int N) {
    __shared__ float2 sh2[4 * D];        // [pair p][k]: {h[2p][k], h[2p+1][k]}

    int j = threadIdx.x;
    float w[D];
#pragma unroll
    for (int k = 0; k < D; k++) w[k] = __ldg(W1 + k * D2 + j);
    float bj = __ldg(b1 + j);
    float ssum = 0.f, ssq = 0.f;

    int ntiles = (N + 7) >> 3;
    for (int t = blockIdx.x; t < ntiles; t += gridDim.x) {
        int i0 = t * 8;
        __syncthreads();                 // protect prev tile's reads
        // stage: thread j -> rows 2m+(j>>6), col j&63, m=0..3
#pragma unroll
        for (int m = 0; m < 4; m++) {
            int r = 2 * m + (j >> 6);
            int k = j & 63;
            int i = i0 + r;
            float v = (i < N) ? g_H[(size_t)i * D + k] : 0.f;
            if (j >> 6) sh2[m * D + k].y = v; else sh2[m * D + k].x = v;
        }
        __syncthreads();
        unsigned long long a0 = 0, a1 = 0, a2 = 0, a3 = 0;
#pragma unroll
        for (int k = 0; k < D; k++) {
            unsigned long long wp = pack_dup(w[k]);
            unsigned long long s0 = *(const unsigned long long*)&sh2[0 * D + k];
            unsigned long long s1 = *(const unsigned long long*)&sh2[1 * D + k];
            unsigned long long s2 = *(const unsigned long long*)&sh2[2 * D + k];
            unsigned long long s3 = *(const unsigned long long*)&sh2[3 * D + k];
            fma2(a0, s0, wp);
            fma2(a1, s1, wp);
            fma2(a2, s2, wp);
            fma2(a3, s3, wp);
        }
        float y[8];
        unpack2(a0, y[0], y[1]);
        unpack2(a1, y[2], y[3]);
        unpack2(a2, y[4], y[5]);
        unpack2(a3, y[6], y[7]);
        int rem = N - i0;
#pragma unroll
        for (int r = 0; r < 8; r++) {
            if (r < rem) {
                float yy = y[r] + bj;
                g_Y1[(size_t)(i0 + r) * D2 + j] = yy;
                ssum += yy; ssq += yy * yy;
            }
        }
    }
    atomicAdd(&g_sum1[j],   ssum);
    atomicAdd(&g_sumsq1[j], ssq);
}

// ---------------- BN finalize ------------------------------------------------
__global__ void k_stats1(const float* __restrict__ gamma,
                         const float* __restrict__ beta, float invN) {
    int j = threadIdx.x;
    float m  = g_sum1[j] * invN;
    float v  = g_sumsq1[j] * invN - m * m;
    float sc = gamma[j] * rsqrtf(v + 1e-5f);
    g_scale1[j] = sc;
    g_shift1[j] = beta[j] - m * sc;
}
__global__ void k_stats2(const float* __restrict__ gamma,
                         const float* __restrict__ beta, float invN) {
    int j = threadIdx.x;
    float m  = g_sum2[j] * invN;
    float v  = g_sumsq2[j] * invN - m * m;
    float sc = gamma[j] * rsqrtf(v + 1e-5f);
    g_scale2[j] = sc;
    g_shift2[j] = beta[j] - m * sc;
}

// ---------------- layer 2: x1 = relu(BN(Y1)); Y2 = x1@W2 + b2 -> d_out -------
// split-K across halves (64 k each), 8-row tiles, rows packed in pairs.
__global__ void __launch_bounds__(128)
k_layer2(const float* __restrict__ W2, const float* __restrict__ b2,
         float* __restrict__ out, int N) {
    __shared__ float2 sx2[4 * D2];                 // [pair p][k 0..127]
    __shared__ unsigned long long sp[4 * D];       // half-1 partials [p][j]
    __shared__ float ssc[D2], ssh[D2];

    int t = threadIdx.x;
    int j = t & 63, half = t >> 6;
    float w[64];
#pragma unroll
    for (int k = 0; k < 64; k++) w[k] = __ldg(W2 + (size_t)(half * 64 + k) * D + j);
    float bj = __ldg(b2 + j);
    ssc[t] = g_scale1[t];
    ssh[t] = g_shift1[t];
    float ssum = 0.f, ssq = 0.f;

    int ntiles = (N + 7) >> 3;
    __syncthreads();
    for (int tt = blockIdx.x; tt < ntiles; tt += gridDim.x) {
        int i0 = tt * 8;
        __syncthreads();                 // protect prev tile's reads
        // stage: thread t owns column k=t, 8 rows (uniform per-m branch)
#pragma unroll
        for (int m = 0; m < 8; m++) {
            int i = i0 + m;
            float v = 0.f;
            if (i < N) {
                float y = g_Y1[(size_t)i * D2 + t];
                v = fmaxf(y * ssc[t] + ssh[t], 0.f);
            }
            if (m & 1) sx2[(m >> 1) * D2 + t].y = v;
            else       sx2[(m >> 1) * D2 + t].x = v;
        }
        __syncthreads();
        unsigned long long a0 = 0, a1 = 0, a2 = 0, a3 = 0;
        const int kb = half * 64;
#pragma unroll
        for (int k = 0; k < 64; k++) {
            unsigned long long wp = pack_dup(w[k]);
            unsigned long long s0 = *(const unsigned long long*)&sx2[0 * D2 + kb + k];
            unsigned long long s1 = *(const unsigned long long*)&sx2[1 * D2 + kb + k];
            unsigned long long s2 = *(const unsigned long long*)&sx2[2 * D2 + kb + k];
            unsigned long long s3 = *(const unsigned long long*)&sx2[3 * D2 + kb + k];
            fma2(a0, s0, wp);
            fma2(a1, s1, wp);
            fma2(a2, s2, wp);
            fma2(a3, s3, wp);
        }
        if (half == 1) {
            sp[0 * D + j] = a0; sp[1 * D + j] = a1;
            sp[2 * D + j] = a2; sp[3 * D + j] = a3;
        }
        __syncthreads();
        if (half == 0) {
            int rem = N - i0;
            unsigned long long mine[4] = {a0, a1, a2, a3};
#pragma unroll
            for (int p = 0; p < 4; p++) {
                float alo, ahi, blo, bhi;
                unpack2(mine[p], alo, ahi);
                unpack2(sp[p * D + j], blo, bhi);
                int r0 = 2 * p, r1 = 2 * p + 1;
                if (r0 < rem) {
                    float y0 = alo + blo + bj;
                    out[(size_t)(i0 + r0) * D + j] = y0;
                    ssum += y0; ssq += y0 * y0;
                }
                if (r1 < rem) {
                    float y1 = ahi + bhi + bj;
                    out[(size_t)(i0 + r1) * D + j] = y1;
                    ssum += y1; ssq += y1 * y1;
                }
            }
        }
    }
    if (half == 0) {
        atomicAdd(&g_sum2[j],   ssum);
        atomicAdd(&g_sumsq2[j], ssq);
    }
}

// ---------------- final BN+ReLU in place on d_out (float4) -------------------
__global__ void k_bnrelu2(float4* __restrict__ out, int total4) {
    int i = blockIdx.x * blockDim.x + threadIdx.x;
    if (i >= total4) return;
    int j0 = (i & 15) * 4;
    float4 v = out[i];
    v.x = fmaxf(v.x * g_scale2[j0 + 0] + g_shift2[j0 + 0], 0.f);
    v.y = fmaxf(v.y * g_scale2[j0 + 1] + g_shift2[j0 + 1], 0.f);
    v.z = fmaxf(v.z * g_scale2[j0 + 2] + g_shift2[j0 + 2], 0.f);
    v.w = fmaxf(v.w * g_scale2[j0 + 3] + g_shift2[j0 + 3], 0.f);
    out[i] = v;
}

// ---------------- launcher ---------------------------------------------------
extern "C" void kernel_launch(void* const* d_in, const int* in_sizes, int n_in,
                              void* d_out, int out_size) {
    const float* node   = (const float*)d_in[0];
    const float* edge   = (const float*)d_in[1];
    const int*   src    = (const int*)  d_in[2];
    const int*   dst    = (const int*)  d_in[3];
    const float* eps    = (const float*)d_in[4];
    const float* W1     = (const float*)d_in[5];
    const float* b1     = (const float*)d_in[6];
    const float* gamma1 = (const float*)d_in[7];
    const float* beta1  = (const float*)d_in[8];
    const float* W2     = (const float*)d_in[9];
    const float* b2     = (const float*)d_in[10];
    const float* gamma2 = (const float*)d_in[11];
    const float* beta2  = (const float*)d_in[12];

    int N = in_sizes[0] / D;
    int E = in_sizes[2];
    float* out = (float*)d_out;
    float invN = 1.0f / (float)N;

    k_zero<<<416, 256>>>(N);
    k_place<<<(E + 255) / 256, 256>>>(dst, E);
    k_gather<<<(N + 7) / 8, 256>>>((const float2*)node, (const float2*)edge,
                                   src, eps, N);
    k_layer1<<<1184, 128>>>(W1, b1, N);
    k_stats1<<<1, 128>>>(gamma1, beta1, invN);
    k_layer2<<<1184, 128>>>(W2, b2, out, N);
    k_stats2<<<1, 64>>>(gamma2, beta2, invN);
    k_bnrelu2<<<(N * 16 + 255) / 256, 256>>>((float4*)out, N * 16);
}

// round 14
// speedup vs baseline: 1.3537x; 1.0008x over previous
#include <cuda_runtime.h>
#include <cstdint>

// Problem constants (fixed by the dataset: N=100000, E=1600000, D=64)
#define NMAX   100000
#define D      64
#define D2     128
#define BINCAP 128     // max degree capacity; E/N=16 avg (Poisson), P(deg>128) ~ 0

// ---------------- scratch (static device globals) ---------------------------
__device__ int    g_cnt[NMAX];                       // per-node in-degree / slot counter
__device__ int    g_bins[(size_t)NMAX * BINCAP];     // 51.2 MB, edge ids bucketed by dst
__device__ float  g_H[(size_t)NMAX * D];             // 25.6 MB, combined input h
__device__ float  g_Y1[(size_t)NMAX * D2];           // 51.2 MB, pre-BN layer-1 output
__device__ float  g_sum1[D2], g_sumsq1[D2];
__device__ float  g_sum2[D],  g_sumsq2[D];
__device__ float  g_scale1[D2], g_shift1[D2];
__device__ float  g_scale2[D],  g_shift2[D];

// ---------------- zero counters + stats --------------------------------------
__global__ void k_zero(int N) {
    int i      = blockIdx.x * blockDim.x + threadIdx.x;
    int stride = gridDim.x * blockDim.x;
    for (int k = i; k < N; k += stride) g_cnt[k] = 0;
    if (i < D2) { g_sum1[i] = 0.f; g_sumsq1[i] = 0.f; }
    if (i < D)  { g_sum2[i] = 0.f; g_sumsq2[i] = 0.f; }
}

// ---------------- bin edges by destination -----------------------------------
__global__ void k_place(const int* __restrict__ dst, int E) {
    int e = blockIdx.x * blockDim.x + threadIdx.x;
    if (e >= E) return;
    int d = __ldg(dst + e);
    int slot = atomicAdd(&g_cnt[d], 1);
    if (slot < BINCAP) g_bins[(size_t)d * BINCAP + slot] = e;
}

// ---------------- gather aggregation: one warp per node ----------------------
// h[n] = (1+eps)*x[n] + (sum_{e: dst=n} (x[src_e] + ef_e)) / max(deg,1)
// Lane l owns float2 chunk l (64 floats = 32 float2 per row).
__global__ void __launch_bounds__(256)
k_gather(const float2* __restrict__ nf2, const float2* __restrict__ ef2,
         const int* __restrict__ src, const float* __restrict__ epsp, int N) {
    int n    = (blockIdx.x * blockDim.x + threadIdx.x) >> 5;
    int lane = threadIdx.x & 31;
    if (n >= N) return;

    int degc = g_cnt[n];
    int deg  = min(degc, BINCAP);
    float2 acc = make_float2(0.f, 0.f);

    for (int base = 0; base < deg; base += 32) {
        int m = min(32, deg - base);
        int eid = 0, s = 0;
        if (lane < m) {
            eid = g_bins[(size_t)n * BINCAP + base + lane];
            s   = __ldg(src + eid);
        }
#pragma unroll 4
        for (int i = 0; i < m; i++) {
            int e  = __shfl_sync(0xffffffffu, eid, i);
            int ss = __shfl_sync(0xffffffffu, s,   i);
            float2 ev = __ldcs(ef2 + (size_t)e  * 32 + lane);  // streamed, evict-first
            float2 nv = __ldg (nf2 + (size_t)ss * 32 + lane);  // hot table, L2
            acc.x += ev.x + nv.x;
            acc.y += ev.y + nv.y;
        }
    }
    float inv  = 1.0f / fmaxf((float)degc, 1.0f);
    float eps1 = 1.0f + __ldg(epsp);
    float2 x = __ldg(nf2 + (size_t)n * 32 + lane);
    float2 h;
    h.x = eps1 * x.x + acc.x * inv;
    h.y = eps1 * x.y + acc.y * inv;
    ((float2*)g_H)[(size_t)n * 32 + lane] = h;
}

// ---------------- packed-f32x2 helpers ---------------------------------------
__device__ __forceinline__ unsigned long long pack_dup(float a) {
    unsigned long long r;
    asm("mov.b64 %0, {%1,%1};" : "=l"(r) : "f"(a));
    return r;
}
__device__ __forceinline__ void fma2(unsigned long long& acc,
                                     unsigned long long a, unsigned long long b) {
    asm("fma.rn.f32x2 %0, %1, %2, %0;" : "+l"(acc) : "l"(a), "l"(b));
}
__device__ __forceinline__ void unpack2(unsigned long long v, float& lo, float& hi) {
    asm("mov.b64 {%0,%1}, %2;" : "=f"(lo), "=f"(hi) : "l"(v));
}

// ---------------- layer 1: Y1 = h@W1 + b1 (+ column stats) -------------------
// 128 threads, thread j owns output column j. 8-row tiles, rows packed in pairs.
__global__ void __launch_bounds__(128)
k_layer1(const float* __restrict__ W1, const float* __restrict__ b1, int N) {
    __shared__ float2 sh2[4 * D];        // [pair p][k]: {h[2p][k], h[2p+1][k]}

    int j = threadIdx.x;
    float w[D];
#pragma unroll
    for (int k = 0; k < D; k++) w[k] = __ldg(W1 + k * D2 + j);
    float bj = __ldg(b1 + j);
    float ssum = 0.f, ssq = 0.f;

    int ntiles = (N + 7) >> 3;
    for (int t = blockIdx.x; t < ntiles; t += gridDim.x) {
        int i0 = t * 8;
        __syncthreads();                 // protect prev tile's reads
        // stage: thread j -> rows 2m+(j>>6), col j&63, m=0..3
#pragma unroll
        for (int m = 0; m < 4; m++) {
            int r = 2 * m + (j >> 6);
            int k = j & 63;
            int i = i0 + r;
            float v = (i < N) ? g_H[(size_t)i * D + k] : 0.f;
            if (j >> 6) sh2[m * D + k].y = v; else sh2[m * D + k].x = v;
        }
        __syncthreads();
        unsigned long long a0 = 0, a1 = 0, a2 = 0, a3 = 0;
#pragma unroll
        for (int k = 0; k < D; k++) {
            unsigned long long wp = pack_dup(w[k]);
            unsigned long long s0 = *(const unsigned long long*)&sh2[0 * D + k];
            unsigned long long s1 = *(const unsigned long long*)&sh2[1 * D + k];
            unsigned long long s2 = *(const unsigned long long*)&sh2[2 * D + k];
            unsigned long long s3 = *(const unsigned long long*)&sh2[3 * D + k];
            fma2(a0, s0, wp);
            fma2(a1, s1, wp);
            fma2(a2, s2, wp);
            fma2(a3, s3, wp);
        }
        float y[8];
        unpack2(a0, y[0], y[1]);
        unpack2(a1, y[2], y[3]);
        unpack2(a2, y[4], y[5]);
        unpack2(a3, y[6], y[7]);
        int rem = N - i0;
#pragma unroll
        for (int r = 0; r < 8; r++) {
            if (r < rem) {
                float yy = y[r] + bj;
                g_Y1[(size_t)(i0 + r) * D2 + j] = yy;
                ssum += yy; ssq += yy * yy;
            }
        }
    }
    atomicAdd(&g_sum1[j],   ssum);
    atomicAdd(&g_sumsq1[j], ssq);
}

// ---------------- BN finalize ------------------------------------------------
__global__ void k_stats1(const float* __restrict__ gamma,
                         const float* __restrict__ beta, float invN) {
    int j = threadIdx.x;
    float m  = g_sum1[j] * invN;
    float v  = g_sumsq1[j] * invN - m * m;
    float sc = gamma[j] * rsqrtf(v + 1e-5f);
    g_scale1[j] = sc;
    g_shift1[j] = beta[j] - m * sc;
}
__global__ void k_stats2(const float* __restrict__ gamma,
                         const float* __restrict__ beta, float invN) {
    int j = threadIdx.x;
    float m  = g_sum2[j] * invN;
    float v  = g_sumsq2[j] * invN - m * m;
    float sc = gamma[j] * rsqrtf(v + 1e-5f);
    g_scale2[j] = sc;
    g_shift2[j] = beta[j] - m * sc;
}

// ---------------- layer 2: x1 = relu(BN(Y1)); Y2 = x1@W2 + b2 -> d_out -------
// split-K across halves (64 k each), 8-row tiles, rows packed in pairs.
__global__ void __launch_bounds__(128)
k_layer2(const float* __restrict__ W2, const float* __restrict__ b2,
         float* __restrict__ out, int N) {
    __shared__ float2 sx2[4 * D2];                 // [pair p][k 0..127]
    __shared__ unsigned long long sp[4 * D];       // half-1 partials [p][j]
    __shared__ float ssc[D2], ssh[D2];

    int t = threadIdx.x;
    int j = t & 63, half = t >> 6;
    float w[64];
#pragma unroll
    for (int k = 0; k < 64; k++) w[k] = __ldg(W2 + (size_t)(half * 64 + k) * D + j);
    float bj = __ldg(b2 + j);
    ssc[t] = g_scale1[t];
    ssh[t] = g_shift1[t];
    float ssum = 0.f, ssq = 0.f;

    int ntiles = (N + 7) >> 3;
    __syncthreads();
    for (int tt = blockIdx.x; tt < ntiles; tt += gridDim.x) {
        int i0 = tt * 8;
        __syncthreads();                 // protect prev tile's reads
        // stage: thread t owns column k=t, 8 rows (uniform per-m branch)
#pragma unroll
        for (int m = 0; m < 8; m++) {
            int i = i0 + m;
            float v = 0.f;
            if (i < N) {
                float y = g_Y1[(size_t)i * D2 + t];
                v = fmaxf(y * ssc[t] + ssh[t], 0.f);
            }
            if (m & 1) sx2[(m >> 1) * D2 + t].y = v;
            else       sx2[(m >> 1) * D2 + t].x = v;
        }
        __syncthreads();
        unsigned long long a0 = 0, a1 = 0, a2 = 0, a3 = 0;
        const int kb = half * 64;
#pragma unroll
        for (int k = 0; k < 64; k++) {
            unsigned long long wp = pack_dup(w[k]);
            unsigned long long s0 = *(const unsigned long long*)&sx2[0 * D2 + kb + k];
            unsigned long long s1 = *(const unsigned long long*)&sx2[1 * D2 + kb + k];
            unsigned long long s2 = *(const unsigned long long*)&sx2[2 * D2 + kb + k];
            unsigned long long s3 = *(const unsigned long long*)&sx2[3 * D2 + kb + k];
            fma2(a0, s0, wp);
            fma2(a1, s1, wp);
            fma2(a2, s2, wp);
            fma2(a3, s3, wp);
        }
        if (half == 1) {
            sp[0 * D + j] = a0; sp[1 * D + j] = a1;
            sp[2 * D + j] = a2; sp[3 * D + j] = a3;
        }
        __syncthreads();
        if (half == 0) {
            int rem = N - i0;
            unsigned long long mine[4] = {a0, a1, a2, a3};
#pragma unroll
            for (int p = 0; p < 4; p++) {
                float alo, ahi, blo, bhi;
                unpack2(mine[p], alo, ahi);
                unpack2(sp[p * D + j], blo, bhi);
                int r0 = 2 * p, r1 = 2 * p + 1;
                if (r0 < rem) {
                    float y0 = alo + blo + bj;
                    out[(size_t)(i0 + r0) * D + j] = y0;
                    ssum += y0; ssq += y0 * y0;
                }
                if (r1 < rem) {
                    float y1 = ahi + bhi + bj;
                    out[(size_t)(i0 + r1) * D + j] = y1;
                    ssum += y1; ssq += y1 * y1;
                }
            }
        }
    }
    if (half == 0) {
        atomicAdd(&g_sum2[j],   ssum);
        atomicAdd(&g_sumsq2[j], ssq);
    }
}

// ---------------- final BN+ReLU in place on d_out (float4) -------------------
__global__ void k_bnrelu2(float4* __restrict__ out, int total4) {
    int i = blockIdx.x * blockDim.x + threadIdx.x;
    if (i >= total4) return;
    int j0 = (i & 15) * 4;
    float4 v = out[i];
    v.x = fmaxf(v.x * g_scale2[j0 + 0] + g_shift2[j0 + 0], 0.f);
    v.y = fmaxf(v.y * g_scale2[j0 + 1] + g_shift2[j0 + 1], 0.f);
    v.z = fmaxf(v.z * g_scale2[j0 + 2] + g_shift2[j0 + 2], 0.f);
    v.w = fmaxf(v.w * g_scale2[j0 + 3] + g_shift2[j0 + 3], 0.f);
    out[i] = v;
}

// ---------------- launcher ---------------------------------------------------
extern "C" void kernel_launch(void* const* d_in, const int* in_sizes, int n_in,
                              void* d_out, int out_size) {
    const float* node   = (const float*)d_in[0];
    const float* edge   = (const float*)d_in[1];
    const int*   src    = (const int*)  d_in[2];
    const int*   dst    = (const int*)  d_in[3];
    const float* eps    = (const float*)d_in[4];
    const float* W1     = (const float*)d_in[5];
    const float* b1     = (const float*)d_in[6];
    const float* gamma1 = (const float*)d_in[7];
    const float* beta1  = (const float*)d_in[8];
    const float* W2     = (const float*)d_in[9];
    const float* b2     = (const float*)d_in[10];
    const float* gamma2 = (const float*)d_in[11];
    const float* beta2  = (const float*)d_in[12];

    int N = in_sizes[0] / D;
    int E = in_sizes[2];
    float* out = (float*)d_out;
    float invN = 1.0f / (float)N;

    k_zero<<<416, 256>>>(N);
    k_place<<<(E + 255) / 256, 256>>>(dst, E);
    k_gather<<<(N + 7) / 8, 256>>>((const float2*)node, (const float2*)edge,
                                   src, eps, N);
    k_layer1<<<1184, 128>>>(W1, b1, N);
    k_stats1<<<1, 128>>>(gamma1, beta1, invN);
    k_layer2<<<1184, 128>>>(W2, b2, out, N);
    k_stats2<<<1, 64>>>(gamma2, beta2, invN);
    k_bnrelu2<<<(N * 16 + 255) / 256, 256>>>((float4*)out, N * 16);
}